// round 1
// baseline (speedup 1.0000x reference)
#include <cuda_runtime.h>
#include <cuda_bf16.h>

#define B_   32
#define S_   2048
#define D_   1536
#define G_   150
#define K_   9
#define R_   32
#define MAXT 150

// Scratch (no allocation allowed): pos->group map and per-group 1/cnt.
__device__ int   g_pos2group[B_ * MAXT];
__device__ float g_inv_cnt[B_ * G_];

// ---------------------------------------------------------------------------
// Kernel 1: per-sample group bookkeeping.
// One block per sample. Computes per-group valid count (idx != -1 and not in
// removal list), keep flag, right-aligned destination positions, fills the
// pos->group map, stores 1/max(cnt,1), and writes the attention output tail.
// ---------------------------------------------------------------------------
__global__ void prep_kernel(const int* __restrict__ patch_idx,
                            const int* __restrict__ remove_idx,
                            float* __restrict__ attn_out)
{
    const int b = blockIdx.x;
    const int t = threadIdx.x;

    __shared__ int s_rem[R_];
    __shared__ int s_keep[G_];
    __shared__ int s_p2g[MAXT];

    if (t < R_)   s_rem[t] = remove_idx[b * R_ + t];
    if (t < MAXT) s_p2g[t] = -1;
    __syncthreads();

    if (t < G_) {
        int cnt = 0;
        const int* gi = patch_idx + (b * G_ + t) * K_;
#pragma unroll
        for (int k = 0; k < K_; k++) {
            int v = gi[k];
            bool valid = (v != -1);
            if (valid) {
                // v >= 0 here, so s_rem entries of -1 can never match.
#pragma unroll
                for (int r = 0; r < R_; r++) {
                    if (s_rem[r] == v) { valid = false; break; }
                }
            }
            cnt += valid ? 1 : 0;
        }
        s_keep[t] = (cnt > 0) ? 1 : 0;
        g_inv_cnt[b * G_ + t] = 1.0f / (float)((cnt > 0) ? cnt : 1);
    }
    __syncthreads();

    if (t == 0) {
        int nk = 0;
        for (int g = 0; g < G_; g++) nk += s_keep[g];
        int pos = MAXT - nk;
        for (int g = 0; g < G_; g++) {
            if (s_keep[g]) { s_p2g[pos] = g; pos++; }
        }
    }
    __syncthreads();

    if (t < MAXT) {
        g_pos2group[b * MAXT + t] = s_p2g[t];
        attn_out[b * MAXT + t] = (s_p2g[t] >= 0) ? 1.0f : 0.0f;
    }
}

// ---------------------------------------------------------------------------
// Kernel 2: one block per output row (b, p).  384 threads, one float4 each
// (384 * 4 = 1536 floats).  Gathers 9 rows, sums, scales by 1/cnt, stores.
// Unmapped positions write zeros (d_out is poisoned before timing).
// ---------------------------------------------------------------------------
__global__ __launch_bounds__(384, 4)
void pool_kernel(const float* __restrict__ h,
                 const int* __restrict__ patch_range,
                 const int* __restrict__ patch_idx,
                 float* __restrict__ out)
{
    const int p = blockIdx.x;   // output position 0..149
    const int b = blockIdx.y;   // sample
    const int t = threadIdx.x;  // 0..383

    __shared__ const float4* s_rows[K_];
    __shared__ float s_inv;
    __shared__ int s_g;

    if (t == 0) s_g = g_pos2group[b * MAXT + p];
    __syncthreads();

    float4* o = reinterpret_cast<float4*>(out + ((size_t)b * MAXT + p) * D_);
    const int g = s_g;
    if (g < 0) {
        o[t] = make_float4(0.f, 0.f, 0.f, 0.f);
        return;
    }

    if (t < K_) {
        int start = patch_range[b * 2 + 0];
        int end   = patch_range[b * 2 + 1];
        int v = patch_idx[(b * G_ + g) * K_ + t];
        int row = (v >= 0) ? (start + v) : (end + 1 + v);  // matches reference wrap
        s_rows[t] = reinterpret_cast<const float4*>(h + ((size_t)b * S_ + row) * (size_t)D_);
    }
    if (t == 0) s_inv = g_inv_cnt[b * G_ + g];
    __syncthreads();

    // 9 independent gathers -> MLP=9, all coalesced within each row.
    float4 acc = make_float4(0.f, 0.f, 0.f, 0.f);
#pragma unroll
    for (int k = 0; k < K_; k++) {
        float4 v = s_rows[k][t];
        acc.x += v.x; acc.y += v.y; acc.z += v.z; acc.w += v.w;
    }
    const float inv = s_inv;
    acc.x *= inv; acc.y *= inv; acc.z *= inv; acc.w *= inv;
    o[t] = acc;
}

extern "C" void kernel_launch(void* const* d_in, const int* in_sizes, int n_in,
                              void* d_out, int out_size)
{
    const float* hidden       = (const float*)d_in[0];  // [B,S,D] f32
    // d_in[1] attention_mask, d_in[2] image_grid_thw: unused by the math
    const int* patch_range    = (const int*)d_in[3];    // [B,2]
    const int* patch_idx      = (const int*)d_in[4];    // [B,G,K]
    const int* remove_idx     = (const int*)d_in[5];    // [B,R]

    float* out      = (float*)d_out;                        // [B,MAXT,D] f32
    float* attn_out = out + (size_t)B_ * MAXT * D_;         // [B,MAXT] as f32 1.0/0.0

    prep_kernel<<<B_, 256>>>(patch_idx, remove_idx, attn_out);

    dim3 grid(MAXT, B_);
    pool_kernel<<<grid, 384>>>(hidden, patch_range, patch_idx, out);
}

// round 2
// speedup vs baseline: 1.0315x; 1.0315x over previous
#include <cuda_runtime.h>
#include <cuda_bf16.h>

#define B_   32
#define S_   2048
#define D_   1536
#define G_   150
#define K_   9
#define R_   32
#define MAXT 150
#define LW   48   // 1536-bit removal bitmap -> 48 x u32

// ---------------------------------------------------------------------------
// Fully fused kernel: one block per output row (b, p), 384 threads.
// Each block redundantly (and cheaply) recomputes its sample's group
// bookkeeping (valid counts via removal bitmap, keep flags, right-aligned
// destination via ballot prefix-scan), then gathers+averages its row.
// No second kernel, no inter-kernel dependency bubble.
// ---------------------------------------------------------------------------
__global__ __launch_bounds__(384, 4)
void fused_pool_kernel(const float* __restrict__ h,
                       const int* __restrict__ patch_range,
                       const int* __restrict__ patch_idx,
                       const int* __restrict__ remove_idx,
                       float* __restrict__ out,
                       float* __restrict__ attn_out)
{
    const int p = blockIdx.x;   // output position 0..149
    const int b = blockIdx.y;   // sample
    const int t = threadIdx.x;  // 0..383

    __shared__ unsigned s_bm[LW];          // removal-set bitmap over [0,1536)
    __shared__ int s_cnt[G_];              // per-group valid count
    __shared__ int s_p2g[MAXT];            // dest position -> group (-1 = empty)
    __shared__ int s_wsum[5];              // per-warp kept-count (warps 0..4 hold t<150)
    __shared__ const float4* s_rows[K_];   // gather row base pointers

    // ---- phase 1: removal bitmap + init ----
    if (t < LW)   s_bm[t] = 0u;
    if (t < MAXT) s_p2g[t] = -1;
    __syncthreads();
    if (t < R_) {
        int v = remove_idx[b * R_ + t];
        if ((unsigned)v < 1536u) atomicOr(&s_bm[v >> 5], 1u << (v & 31));
    }
    __syncthreads();

    // ---- phase 2: per-group valid counts ----
    int keep = 0;
    if (t < G_) {
        const int* gi = patch_idx + (b * G_ + t) * K_;
        int cnt = 0;
#pragma unroll
        for (int k = 0; k < K_; k++) {
            int v = gi[k];
            bool valid = (v != -1);
            if (valid && (unsigned)v < 1536u)
                valid = ((s_bm[v >> 5] >> (v & 31)) & 1u) == 0u;
            cnt += valid ? 1 : 0;
        }
        s_cnt[t] = cnt;
        keep = (cnt > 0) ? 1 : 0;
    }

    // ---- phase 3: ballot prefix-scan -> right-aligned dest, scatter p2g ----
    const unsigned bmask = __ballot_sync(0xFFFFFFFFu, keep);
    const int w = t >> 5, lane = t & 31;
    if (lane == 0 && w < 5) s_wsum[w] = __popc(bmask);
    __syncthreads();

    if (keep) {  // implies t < 150, so w <= 4
        int nk = s_wsum[0] + s_wsum[1] + s_wsum[2] + s_wsum[3] + s_wsum[4];
        int before = __popc(bmask & ((1u << lane) - 1u));
        for (int w2 = 0; w2 < w; w2++) before += s_wsum[w2];
        s_p2g[MAXT - nk + before] = t;
    }
    __syncthreads();

    // ---- phase 4: this block's row ----
    const int g = s_p2g[p];
    if (t == 0) attn_out[b * MAXT + p] = (g >= 0) ? 1.0f : 0.0f;

    float4* o = reinterpret_cast<float4*>(out + ((size_t)(b * MAXT + p)) * D_);
    if (g < 0) {                       // uniform per block
        o[t] = make_float4(0.f, 0.f, 0.f, 0.f);
        return;
    }

    if (t < K_) {
        int start = patch_range[b * 2 + 0];
        int end   = patch_range[b * 2 + 1];
        int v = patch_idx[(b * G_ + g) * K_ + t];
        int row = (v >= 0) ? (start + v) : (end + 1 + v);   // reference wrap
        s_rows[t] = reinterpret_cast<const float4*>(h + ((size_t)(b * S_ + row)) * (size_t)D_);
    }
    __syncthreads();

    const float inv = 1.0f / (float)max(s_cnt[g], 1);

    // 9 independent coalesced gathers -> MLP=9
    float4 acc = make_float4(0.f, 0.f, 0.f, 0.f);
#pragma unroll
    for (int k = 0; k < K_; k++) {
        float4 v = s_rows[k][t];
        acc.x += v.x; acc.y += v.y; acc.z += v.z; acc.w += v.w;
    }
    acc.x *= inv; acc.y *= inv; acc.z *= inv; acc.w *= inv;
    o[t] = acc;
}

extern "C" void kernel_launch(void* const* d_in, const int* in_sizes, int n_in,
                              void* d_out, int out_size)
{
    const float* hidden    = (const float*)d_in[0];  // [B,S,D] f32
    // d_in[1] attention_mask, d_in[2] image_grid_thw: unused by the math
    const int* patch_range = (const int*)d_in[3];    // [B,2]
    const int* patch_idx   = (const int*)d_in[4];    // [B,G,K]
    const int* remove_idx  = (const int*)d_in[5];    // [B,R]

    float* out      = (float*)d_out;                 // [B,MAXT,D]
    float* attn_out = out + (size_t)B_ * MAXT * D_;  // [B,MAXT]

    dim3 grid(MAXT, B_);
    fused_pool_kernel<<<grid, 384>>>(hidden, patch_range, patch_idx, remove_idx,
                                     out, attn_out);
}

// round 4
// speedup vs baseline: 1.1445x; 1.1096x over previous
#include <cuda_runtime.h>
#include <cuda_bf16.h>

#define B_     32
#define S_     2048
#define D_     1536
#define G_     150
#define K_     9
#define R_     32
#define MAXT   150
#define LW     48     // 1536-bit removal bitmap -> 48 x u32
#define PPB    10     // positions per block
#define CHUNKS 15     // PPB * CHUNKS == MAXT

// ---------------------------------------------------------------------------
// One block per (chunk of 10 output positions, sample). 384 threads.
// Prep (removal bitmap, valid counts, right-aligned dest scan) runs once per
// block (15x per sample), then all 90 gather-row pointers are staged in smem
// and the main loop is pure LDG/FADD/STG with no syncs.
// ---------------------------------------------------------------------------
__global__ __launch_bounds__(384, 4)
void fused_pool_kernel(const float* __restrict__ h,
                       const int* __restrict__ patch_range,
                       const int* __restrict__ patch_idx,
                       const int* __restrict__ remove_idx,
                       float* __restrict__ out,
                       float* __restrict__ attn_out)
{
    const int c = blockIdx.x;   // position chunk 0..14
    const int b = blockIdx.y;   // sample
    const int t = threadIdx.x;  // 0..383

    __shared__ unsigned s_bm[LW];
    __shared__ int s_cnt[G_];
    __shared__ int s_p2g[MAXT];
    __shared__ int s_wsum[5];
    __shared__ const float4* s_rows[PPB * K_];
    __shared__ float s_inv[PPB];

    // ---- prep: removal bitmap ----
    if (t < LW)   s_bm[t] = 0u;
    if (t < MAXT) s_p2g[t] = -1;
    __syncthreads();
    if (t < R_) {
        int v = remove_idx[b * R_ + t];
        if ((unsigned)v < 1536u) atomicOr(&s_bm[v >> 5], 1u << (v & 31));
    }
    __syncthreads();

    // ---- prep: per-group valid counts ----
    int keep = 0;
    if (t < G_) {
        const int* gi = patch_idx + (b * G_ + t) * K_;
        int cnt = 0;
#pragma unroll
        for (int k = 0; k < K_; k++) {
            int v = gi[k];
            bool valid = (v != -1);
            if (valid && (unsigned)v < 1536u)
                valid = ((s_bm[v >> 5] >> (v & 31)) & 1u) == 0u;
            cnt += valid ? 1 : 0;
        }
        s_cnt[t] = cnt;
        keep = (cnt > 0) ? 1 : 0;
    }

    // ---- prep: ballot prefix scan -> right-aligned dest ----
    const unsigned bmask = __ballot_sync(0xFFFFFFFFu, keep);
    const int w = t >> 5, lane = t & 31;
    if (lane == 0 && w < 5) s_wsum[w] = __popc(bmask);
    __syncthreads();
    if (keep) {  // implies t < 150 => w <= 4
        int nk = s_wsum[0] + s_wsum[1] + s_wsum[2] + s_wsum[3] + s_wsum[4];
        int before = __popc(bmask & ((1u << lane) - 1u));
        for (int w2 = 0; w2 < w; w2++) before += s_wsum[w2];
        s_p2g[MAXT - nk + before] = t;
    }
    __syncthreads();

    // ---- setup: stage row pointers + scales for this block's 10 positions ----
    if (t < PPB) {
        int p = c * PPB + t;
        int g = s_p2g[p];
        s_inv[t] = (g >= 0) ? 1.0f / (float)max(s_cnt[g], 1) : 0.0f;
        attn_out[b * MAXT + p] = (g >= 0) ? 1.0f : 0.0f;
    }
    if (t < PPB * K_) {
        int i = t / K_, k = t - i * K_;
        int p = c * PPB + i;
        int g = s_p2g[p];
        const float* base = h + (size_t)b * S_ * D_;
        int row = 0;  // dummy (inv=0 zeroes the result) for dropped positions
        if (g >= 0) {
            int start = patch_range[b * 2 + 0];
            int end   = patch_range[b * 2 + 1];
            int v = patch_idx[(b * G_ + g) * K_ + k];
            row = (v >= 0) ? (start + v) : (end + 1 + v);   // reference wrap
        }
        s_rows[t] = reinterpret_cast<const float4*>(base + (size_t)row * D_);
    }
    __syncthreads();

    // ---- main loop: pure gather/accumulate/store, branchless ----
    float4* obase = reinterpret_cast<float4*>(out + ((size_t)(b * MAXT) + c * PPB) * D_);
#pragma unroll 2
    for (int i = 0; i < PPB; i++) {
        const float inv = s_inv[i];
        float4 acc = make_float4(0.f, 0.f, 0.f, 0.f);
#pragma unroll
        for (int k = 0; k < K_; k++) {
            float4 v = s_rows[i * K_ + k][t];
            acc.x += v.x; acc.y += v.y; acc.z += v.z; acc.w += v.w;
        }
        acc.x *= inv; acc.y *= inv; acc.z *= inv; acc.w *= inv;
        obase[(size_t)i * (D_ / 4) + t] = acc;
    }
}

extern "C" void kernel_launch(void* const* d_in, const int* in_sizes, int n_in,
                              void* d_out, int out_size)
{
    const float* hidden    = (const float*)d_in[0];  // [B,S,D] f32
    // d_in[1] attention_mask, d_in[2] image_grid_thw: unused by the math
    const int* patch_range = (const int*)d_in[3];    // [B,2]
    const int* patch_idx   = (const int*)d_in[4];    // [B,G,K]
    const int* remove_idx  = (const int*)d_in[5];    // [B,R]

    float* out      = (float*)d_out;                 // [B,MAXT,D]
    float* attn_out = out + (size_t)B_ * MAXT * D_;  // [B,MAXT]

    dim3 grid(CHUNKS, B_);
    fused_pool_kernel<<<grid, 384>>>(hidden, patch_range, patch_idx, remove_idx,
                                     out, attn_out);
}